// round 10
// baseline (speedup 1.0000x reference)
#include <cuda_runtime.h>
#include <cuda_bf16.h>
#include <cstdint>

// VQ nearest-codebook search via warp-level mma.sync (HMMA, baseline PTX —
// harness targets compute_103, no tcgen05/'a' features available).
//   inputs [16,64,64,64] NCHW fp32, codebook [1024,64] fp32
//   out[n] (as float32) = argmin_k ||x_n - e_k||^2
//                       = argmax_k ( x_n.e_k - 0.5||e_k||^2 )
// bf16 triple-split x = b0+b1+b2; 6 accumulating bf16 MMA passes into fp32.
// R10: pass-major MMA order (16 independent accumulators between reuses of
// any C fragment -> no HMMA RAW chains) + ldmatrix.x4 B loads (2 n8/instr).

#define NUM_CODES 1024
#define DIM       64
#define M_TILE    128
#define N_CHUNK   128
#define CHUNKS    8
#define THREADS   256
#define N_ROWS    65536
#define HW        4096
#define TILEB     16384            // one [128 codes/rows][64 bf16] tile

// smem layout (relative to 1024-aligned base)
#define SM_H      0                // 1024 floats (-0.5||e||^2)
#define SM_A      4096             // 3 comps x 16 KB
#define SM_B      (SM_A + 3 * TILEB)   // 2 bufs x 3 comps x 16 KB
#define SM_TOTAL  (SM_B + 6 * TILEB)   // 151552
#define SM_ALLOC  (SM_TOTAL + 1024)

__device__ float g_h[NUM_CODES];                       // -0.5*||e_k||^2
__device__ __align__(16) unsigned char g_bsplit[3 * CHUNKS * TILEB];

#define SW128(o) ((o) ^ (((o) >> 3) & 0x70))

__device__ __forceinline__ uint32_t smem_u32(const void* p) {
    uint32_t a;
    asm("{ .reg .u64 t; cvta.to.shared.u64 t, %1; cvt.u32.u64 %0, t; }"
        : "=r"(a) : "l"(p));
    return a;
}

#define LDSM_X4(r, a) \
    asm volatile("ldmatrix.sync.aligned.m8n8.x4.shared.b16 {%0,%1,%2,%3}, [%4];" \
        : "=r"((r)[0]), "=r"((r)[1]), "=r"((r)[2]), "=r"((r)[3]) : "r"(a))
#define MMA(c, A, B) \
    asm volatile("mma.sync.aligned.m16n8k16.row.col.f32.bf16.bf16.f32 " \
        "{%0,%1,%2,%3}, {%4,%5,%6,%7}, {%8,%9}, {%0,%1,%2,%3};" \
        : "+f"((c)[0]), "+f"((c)[1]), "+f"((c)[2]), "+f"((c)[3]) \
        : "r"((A)[0]), "r"((A)[1]), "r"((A)[2]), "r"((A)[3]), \
          "r"((B)[0]), "r"((B)[1]))
#define CP16(dst, src) \
    asm volatile("cp.async.cg.shared.global [%0], [%1], 16;" :: "r"(dst), "l"(src))
#define CP_COMMIT() asm volatile("cp.async.commit_group;" ::: "memory")
#define CP_WAIT(n)  asm volatile("cp.async.wait_group %0;" :: "n"(n) : "memory")

__device__ __forceinline__ uint32_t pack_bf16(__nv_bfloat16 lo, __nv_bfloat16 hi) {
    return ((uint32_t)__bfloat16_as_ushort(hi) << 16) | __bfloat16_as_ushort(lo);
}
__device__ __forceinline__ void split3(float x, __nv_bfloat16& c0,
                                       __nv_bfloat16& c1, __nv_bfloat16& c2) {
    c0 = __float2bfloat16(x);
    float r0 = x - __bfloat162float(c0);
    c1 = __float2bfloat16(r0);
    float r1 = r0 - __bfloat162float(c1);
    c2 = __float2bfloat16(r1);
}

// ---------------------------------------------------------------------------
// Prep: split codebook into 3 bf16 comps, pre-swizzled tiles; -0.5 norms.
// ---------------------------------------------------------------------------
__global__ void vq_prep(const float* __restrict__ cb) {
    int j = blockIdx.x * blockDim.x + threadIdx.x;   // code 0..1023
    if (j >= NUM_CODES) return;
    int chunk = j >> 7, jr = j & 127;
    float nrm = 0.f;
    for (int dp = 0; dp < 32; ++dp) {
        float x0 = cb[(size_t)j * DIM + 2 * dp];
        float x1 = cb[(size_t)j * DIM + 2 * dp + 1];
        nrm = fmaf(x0, x0, nrm);
        nrm = fmaf(x1, x1, nrm);
        __nv_bfloat16 a0, a1, a2, b0, b1, b2;
        split3(x0, a0, a1, a2);
        split3(x1, b0, b1, b2);
        uint32_t sw = SW128((uint32_t)(jr * 128 + dp * 4));
        *(uint32_t*)&g_bsplit[(0 * CHUNKS + chunk) * TILEB + sw] = pack_bf16(a0, b0);
        *(uint32_t*)&g_bsplit[(1 * CHUNKS + chunk) * TILEB + sw] = pack_bf16(a1, b1);
        *(uint32_t*)&g_bsplit[(2 * CHUNKS + chunk) * TILEB + sw] = pack_bf16(a2, b2);
    }
    g_h[j] = -0.5f * nrm;
}

// ---------------------------------------------------------------------------
// Main kernel
// ---------------------------------------------------------------------------
__device__ __forceinline__ void cp_chunk(uint32_t sb, int c, int bb, int tid) {
#pragma unroll
    for (int t = 0; t < 3; ++t) {
#pragma unroll
        for (int i = 0; i < 4; ++i) {
            int idx = i * THREADS + tid;
            uint32_t dst = sb + SM_B + (bb * 3 + t) * TILEB + idx * 16;
            const unsigned char* src = &g_bsplit[(t * CHUNKS + c) * TILEB + idx * 16];
            CP16(dst, src);
        }
    }
}

__global__ __launch_bounds__(THREADS)
void vq_mma_kernel(const float* __restrict__ in, float* __restrict__ out) {
    extern __shared__ char smraw[];
    const uint32_t sbr = smem_u32(smraw);
    const uint32_t sb  = (sbr + 1023u) & ~1023u;    // 1K-align for swizzle
    char* sm = smraw + (sb - sbr);

    const int tid  = threadIdx.x;
    const int wid  = tid >> 5;
    const int lane = tid & 31;

    // -0.5||e||^2 -> smem
    float* sh = (float*)(sm + SM_H);
    for (int i = tid; i < NUM_CODES; i += THREADS) sh[i] = g_h[i];

    // build A: 128 rows x 64 ch, triple-split bf16, swizzled
    const int rowBase = blockIdx.x * M_TILE;
    const int b   = rowBase >> 12;
    const int hw0 = rowBase & (HW - 1);
    const float* xin = in + ((size_t)b * DIM * HW) + hw0;
#pragma unroll
    for (int i = 0; i < 16; ++i) {
        int idx = i * THREADS + tid;
        int r = idx & 127, dp = idx >> 7;
        float x0 = xin[(size_t)(2 * dp) * HW + r];
        float x1 = xin[(size_t)(2 * dp + 1) * HW + r];
        __nv_bfloat16 a0, a1, a2, b0, b1, b2;
        split3(x0, a0, a1, a2);
        split3(x1, b0, b1, b2);
        uint32_t sw = SW128((uint32_t)(r * 128 + dp * 4));
        *(uint32_t*)(sm + SM_A + 0 * TILEB + sw) = pack_bf16(a0, b0);
        *(uint32_t*)(sm + SM_A + 1 * TILEB + sw) = pack_bf16(a1, b1);
        *(uint32_t*)(sm + SM_A + 2 * TILEB + sw) = pack_bf16(a2, b2);
    }

    // prefetch B chunk 0
    cp_chunk(sb, 0, 0, tid);
    CP_COMMIT();

    __syncthreads();      // A + h ready

    // A fragments in registers: warp w = rows w*16..w*16+15.
    uint32_t Af[3][4][4];
    {
        const int arow = wid * 16 + (lane & 15);
        const uint32_t colb = (uint32_t)((lane >> 4) * 16);
#pragma unroll
        for (int t = 0; t < 3; ++t)
#pragma unroll
            for (int ks = 0; ks < 4; ++ks) {
                uint32_t off = (uint32_t)(arow * 128)
                             + ((colb + ks * 32) ^ ((uint32_t)(arow & 7) << 4));
                LDSM_X4(Af[t][ks], sb + SM_A + t * TILEB + off);
            }
    }

    // B ldmatrix.x4 lane geometry: all 32 lanes.
    //   r7 = code row % 8; ms = k-half (0: k0-7, 1: k8-15); j2 = n8 block +0/+1
    const int r7 = lane & 7;
    const int ms = (lane >> 3) & 1;
    const int j2 = lane >> 4;
    const uint32_t blane = (uint32_t)(j2 * 1024 + r7 * 128);
    const int colOff = 2 * (lane & 3);

    float best0 = -3.402823466e38f, best1 = -3.402823466e38f;
    int   bi0 = 0, bi1 = 0;

    for (int c = 0; c < CHUNKS; ++c) {
        const int bb = c & 1;
        if (c) __syncthreads();                // all done reading buf bb
        if (c + 1 < CHUNKS) {
            cp_chunk(sb, c + 1, bb ^ 1, tid);
            CP_COMMIT();
            CP_WAIT(1);                        // chunk c arrived
        } else {
            CP_WAIT(0);
        }
        __syncthreads();                       // chunk c visible to all

        // C init = -0.5||e||^2 (rows lane>>2 and +8 share columns)
        float C[16][4];
#pragma unroll
        for (int n8 = 0; n8 < 16; ++n8) {
            float2 h2 = *(const float2*)&sh[c * N_CHUNK + n8 * 8 + colOff];
            C[n8][0] = h2.x; C[n8][1] = h2.y;
            C[n8][2] = h2.x; C[n8][3] = h2.y;
        }

#pragma unroll
        for (int ks = 0; ks < 4; ++ks) {
            const uint32_t kc = (uint32_t)((ks * 32 + ms * 16) ^ (r7 << 4));
#pragma unroll
            for (int t = 0; t < 3; ++t) {      // B component
                const uint32_t bbase = sb + SM_B + (bb * 3 + t) * TILEB
                                     + blane + kc;
                uint32_t Bt[8][4];             // 16 n8 frags (2 per LDSM_X4)
#pragma unroll
                for (int n16 = 0; n16 < 8; ++n16)
                    LDSM_X4(Bt[n16], bbase + (uint32_t)(n16 * 2048));
                // passes using e_t: x_0..x_{2-t}; inner n-loop -> 16
                // independent accumulators between reuses of any C frag.
#pragma unroll
                for (int at = 0; at < 3 - t; ++at) {
#pragma unroll
                    for (int n16 = 0; n16 < 8; ++n16) {
                        MMA(C[2 * n16],     Af[at][ks], &Bt[n16][0]);
                        MMA(C[2 * n16 + 1], Af[at][ks], &Bt[n16][2]);
                    }
                }
            }
        }

        // epilogue: argmax over this chunk (codes ascending -> first-min tie)
#pragma unroll
        for (int n8 = 0; n8 < 16; ++n8) {
            const int code = c * N_CHUNK + n8 * 8 + colOff;
            if (C[n8][0] > best0) { best0 = C[n8][0]; bi0 = code; }
            if (C[n8][1] > best0) { best0 = C[n8][1]; bi0 = code + 1; }
            if (C[n8][2] > best1) { best1 = C[n8][2]; bi1 = code; }
            if (C[n8][3] > best1) { best1 = C[n8][3]; bi1 = code + 1; }
        }
    }

    // cross-lane reduce among the 4 lanes sharing each row
#pragma unroll
    for (int off = 1; off <= 2; off <<= 1) {
        float v0 = __shfl_xor_sync(0xFFFFFFFFu, best0, off);
        int   i0 = __shfl_xor_sync(0xFFFFFFFFu, bi0,   off);
        if (v0 > best0 || (v0 == best0 && i0 < bi0)) { best0 = v0; bi0 = i0; }
        float v1 = __shfl_xor_sync(0xFFFFFFFFu, best1, off);
        int   i1 = __shfl_xor_sync(0xFFFFFFFFu, bi1,   off);
        if (v1 > best1 || (v1 == best1 && i1 < bi1)) { best1 = v1; bi1 = i1; }
    }
    if ((lane & 3) == 0) {
        const int r = lane >> 2;
        out[rowBase + wid * 16 + r]     = (float)bi0;
        out[rowBase + wid * 16 + r + 8] = (float)bi1;
    }
}

// ---------------------------------------------------------------------------
// Harness entry
// ---------------------------------------------------------------------------
extern "C" void kernel_launch(void* const* d_in, const int* in_sizes, int n_in,
                              void* d_out, int out_size) {
    const float* inp = (const float*)d_in[0];
    const float* cb  = (const float*)d_in[1];
    if (in_sizes[0] == NUM_CODES * DIM && in_sizes[1] != NUM_CODES * DIM) {
        const float* tmp = inp; inp = cb; cb = tmp;
    }
    float* out = (float*)d_out;

    cudaFuncSetAttribute(vq_mma_kernel,
                         cudaFuncAttributeMaxDynamicSharedMemorySize, SM_ALLOC);
    vq_prep<<<NUM_CODES / 256, 256>>>(cb);
    vq_mma_kernel<<<N_ROWS / M_TILE, THREADS, SM_ALLOC>>>(inp, out);
}

// round 11
// speedup vs baseline: 1.1575x; 1.1575x over previous
#include <cuda_runtime.h>
#include <cuda_bf16.h>
#include <cstdint>

// VQ nearest-codebook search via warp-level mma.sync (HMMA, baseline PTX —
// harness targets compute_103, no tcgen05/'a' features available).
//   inputs [16,64,64,64] NCHW fp32, codebook [1024,64] fp32
//   out[n] (as float32) = argmin_k ||x_n - e_k||^2
//                       = argmax_k ( x_n.e_k - 0.5||e_k||^2 )
// bf16 triple-split x = b0+b1+b2; 6 accumulating bf16 MMA passes into fp32.
// R11: 2 CTAs/SM (N_CHUNK=64 -> smem 101KB; launch_bounds(256,2) -> <=128
// regs) so 4 warps/SMSP cover the tensor-pipe gaps that held duty at 60%.

#define NUM_CODES 1024
#define DIM       64
#define M_TILE    128
#define N_CHUNK   64
#define CHUNKS    16
#define THREADS   256
#define N_ROWS    65536
#define HW        4096
#define ATILE     16384            // [128 rows][64 bf16] A tile
#define BTILE     8192             // [64 codes][64 bf16] B tile

// smem layout (relative to 1024-aligned base)
#define SM_H      0                          // 1024 floats (-0.5||e||^2)
#define SM_A      4096                       // 3 comps x 16 KB
#define SM_B      (SM_A + 3 * ATILE)         // 2 bufs x 3 comps x 8 KB
#define SM_TOTAL  (SM_B + 6 * BTILE)         // 101376
#define SM_ALLOC  (SM_TOTAL + 1024)

__device__ float g_h[NUM_CODES];                       // -0.5*||e_k||^2
__device__ __align__(16) unsigned char g_bsplit[3 * CHUNKS * BTILE];

#define SW128(o) ((o) ^ (((o) >> 3) & 0x70))

__device__ __forceinline__ uint32_t smem_u32(const void* p) {
    uint32_t a;
    asm("{ .reg .u64 t; cvta.to.shared.u64 t, %1; cvt.u32.u64 %0, t; }"
        : "=r"(a) : "l"(p));
    return a;
}

#define LDSM_X4(r, a) \
    asm volatile("ldmatrix.sync.aligned.m8n8.x4.shared.b16 {%0,%1,%2,%3}, [%4];" \
        : "=r"((r)[0]), "=r"((r)[1]), "=r"((r)[2]), "=r"((r)[3]) : "r"(a))
#define MMA(c, A, B) \
    asm volatile("mma.sync.aligned.m16n8k16.row.col.f32.bf16.bf16.f32 " \
        "{%0,%1,%2,%3}, {%4,%5,%6,%7}, {%8,%9}, {%0,%1,%2,%3};" \
        : "+f"((c)[0]), "+f"((c)[1]), "+f"((c)[2]), "+f"((c)[3]) \
        : "r"((A)[0]), "r"((A)[1]), "r"((A)[2]), "r"((A)[3]), \
          "r"((B)[0]), "r"((B)[1]))
#define CP16(dst, src) \
    asm volatile("cp.async.cg.shared.global [%0], [%1], 16;" :: "r"(dst), "l"(src))
#define CP_COMMIT() asm volatile("cp.async.commit_group;" ::: "memory")
#define CP_WAIT(n)  asm volatile("cp.async.wait_group %0;" :: "n"(n) : "memory")

__device__ __forceinline__ uint32_t pack_bf16(__nv_bfloat16 lo, __nv_bfloat16 hi) {
    return ((uint32_t)__bfloat16_as_ushort(hi) << 16) | __bfloat16_as_ushort(lo);
}
__device__ __forceinline__ void split3(float x, __nv_bfloat16& c0,
                                       __nv_bfloat16& c1, __nv_bfloat16& c2) {
    c0 = __float2bfloat16(x);
    float r0 = x - __bfloat162float(c0);
    c1 = __float2bfloat16(r0);
    float r1 = r0 - __bfloat162float(c1);
    c2 = __float2bfloat16(r1);
}

// ---------------------------------------------------------------------------
// Prep: split codebook into 3 bf16 comps, pre-swizzled [64-code] tiles; norms.
// 4 lanes per code (16 dims each) + shfl reduction. grid 16 x 256.
// ---------------------------------------------------------------------------
__global__ void vq_prep(const float* __restrict__ cb) {
    int g = blockIdx.x * blockDim.x + threadIdx.x;   // 0..4095
    int j = g >> 2;                                  // code
    int q = g & 3;                                   // dim quarter
    int chunk = j >> 6, jr = j & 63;
    float nrm = 0.f;
#pragma unroll
    for (int i = 0; i < 8; ++i) {
        int dp = q * 8 + i;                          // dim pair
        float x0 = cb[(size_t)j * DIM + 2 * dp];
        float x1 = cb[(size_t)j * DIM + 2 * dp + 1];
        nrm = fmaf(x0, x0, nrm);
        nrm = fmaf(x1, x1, nrm);
        __nv_bfloat16 a0, a1, a2, b0, b1, b2;
        split3(x0, a0, a1, a2);
        split3(x1, b0, b1, b2);
        uint32_t sw = SW128((uint32_t)(jr * 128 + dp * 4));
        *(uint32_t*)&g_bsplit[(0 * CHUNKS + chunk) * BTILE + sw] = pack_bf16(a0, b0);
        *(uint32_t*)&g_bsplit[(1 * CHUNKS + chunk) * BTILE + sw] = pack_bf16(a1, b1);
        *(uint32_t*)&g_bsplit[(2 * CHUNKS + chunk) * BTILE + sw] = pack_bf16(a2, b2);
    }
    nrm += __shfl_xor_sync(0xFFFFFFFFu, nrm, 1);
    nrm += __shfl_xor_sync(0xFFFFFFFFu, nrm, 2);
    if (q == 0) g_h[j] = -0.5f * nrm;
}

// ---------------------------------------------------------------------------
// Main kernel
// ---------------------------------------------------------------------------
__device__ __forceinline__ void cp_chunk(uint32_t sb, int c, int bb, int tid) {
#pragma unroll
    for (int t = 0; t < 3; ++t) {
#pragma unroll
        for (int i = 0; i < 2; ++i) {       // 512 float4 per 8KB tile
            int idx = i * THREADS + tid;
            uint32_t dst = sb + SM_B + (bb * 3 + t) * BTILE + idx * 16;
            const unsigned char* src = &g_bsplit[(t * CHUNKS + c) * BTILE + idx * 16];
            CP16(dst, src);
        }
    }
}

__global__ __launch_bounds__(THREADS, 2)
void vq_mma_kernel(const float* __restrict__ in, float* __restrict__ out) {
    extern __shared__ char smraw[];
    const uint32_t sbr = smem_u32(smraw);
    const uint32_t sb  = (sbr + 1023u) & ~1023u;    // 1K-align for swizzle
    char* sm = smraw + (sb - sbr);

    const int tid  = threadIdx.x;
    const int wid  = tid >> 5;
    const int lane = tid & 31;

    // -0.5||e||^2 -> smem
    float* sh = (float*)(sm + SM_H);
    for (int i = tid; i < NUM_CODES; i += THREADS) sh[i] = g_h[i];

    // build A: 128 rows x 64 ch, triple-split bf16, swizzled
    const int rowBase = blockIdx.x * M_TILE;
    const int b   = rowBase >> 12;
    const int hw0 = rowBase & (HW - 1);
    const float* xin = in + ((size_t)b * DIM * HW) + hw0;
#pragma unroll
    for (int i = 0; i < 16; ++i) {
        int idx = i * THREADS + tid;
        int r = idx & 127, dp = idx >> 7;
        float x0 = xin[(size_t)(2 * dp) * HW + r];
        float x1 = xin[(size_t)(2 * dp + 1) * HW + r];
        __nv_bfloat16 a0, a1, a2, b0, b1, b2;
        split3(x0, a0, a1, a2);
        split3(x1, b0, b1, b2);
        uint32_t sw = SW128((uint32_t)(r * 128 + dp * 4));
        *(uint32_t*)(sm + SM_A + 0 * ATILE + sw) = pack_bf16(a0, b0);
        *(uint32_t*)(sm + SM_A + 1 * ATILE + sw) = pack_bf16(a1, b1);
        *(uint32_t*)(sm + SM_A + 2 * ATILE + sw) = pack_bf16(a2, b2);
    }

    // prefetch B chunk 0
    cp_chunk(sb, 0, 0, tid);
    CP_COMMIT();

    __syncthreads();      // A + h ready

    // A fragments in registers: warp w = rows w*16..w*16+15.  48 regs.
    uint32_t Af[3][4][4];
    {
        const int arow = wid * 16 + (lane & 15);
        const uint32_t colb = (uint32_t)((lane >> 4) * 16);
#pragma unroll
        for (int t = 0; t < 3; ++t)
#pragma unroll
            for (int ks = 0; ks < 4; ++ks) {
                uint32_t off = (uint32_t)(arow * 128)
                             + ((colb + ks * 32) ^ ((uint32_t)(arow & 7) << 4));
                LDSM_X4(Af[t][ks], sb + SM_A + t * ATILE + off);
            }
    }

    // B ldmatrix.x4 lane geometry
    const int r7 = lane & 7;
    const int ms = (lane >> 3) & 1;
    const int j2 = lane >> 4;
    const uint32_t blane = (uint32_t)(j2 * 1024 + r7 * 128);
    const int colOff = 2 * (lane & 3);

    float best0 = -3.402823466e38f, best1 = -3.402823466e38f;
    int   bi0 = 0, bi1 = 0;

    for (int c = 0; c < CHUNKS; ++c) {
        const int bb = c & 1;
        if (c) __syncthreads();                // all done reading buf bb
        if (c + 1 < CHUNKS) {
            cp_chunk(sb, c + 1, bb ^ 1, tid);
            CP_COMMIT();
            CP_WAIT(1);                        // chunk c arrived
        } else {
            CP_WAIT(0);
        }
        __syncthreads();                       // chunk c visible to all

        // C init = -0.5||e||^2
        float C[8][4];
#pragma unroll
        for (int n8 = 0; n8 < 8; ++n8) {
            float2 h2 = *(const float2*)&sh[c * N_CHUNK + n8 * 8 + colOff];
            C[n8][0] = h2.x; C[n8][1] = h2.y;
            C[n8][2] = h2.x; C[n8][3] = h2.y;
        }

#pragma unroll
        for (int ks = 0; ks < 4; ++ks) {
            const uint32_t kc = (uint32_t)((ks * 32 + ms * 16) ^ (r7 << 4));
#pragma unroll
            for (int t = 0; t < 3; ++t) {      // B component
                const uint32_t bbase = sb + SM_B + (bb * 3 + t) * BTILE
                                     + blane + kc;
                uint32_t Bt[4][4];             // 8 n8 frags (2 per LDSM_X4)
#pragma unroll
                for (int n16 = 0; n16 < 4; ++n16)
                    LDSM_X4(Bt[n16], bbase + (uint32_t)(n16 * 2048));
#pragma unroll
                for (int at = 0; at < 3 - t; ++at) {
#pragma unroll
                    for (int n16 = 0; n16 < 4; ++n16) {
                        MMA(C[2 * n16],     Af[at][ks], &Bt[n16][0]);
                        MMA(C[2 * n16 + 1], Af[at][ks], &Bt[n16][2]);
                    }
                }
            }
        }

        // epilogue: argmax over this chunk (codes ascending -> first-min tie)
#pragma unroll
        for (int n8 = 0; n8 < 8; ++n8) {
            const int code = c * N_CHUNK + n8 * 8 + colOff;
            if (C[n8][0] > best0) { best0 = C[n8][0]; bi0 = code; }
            if (C[n8][1] > best0) { best0 = C[n8][1]; bi0 = code + 1; }
            if (C[n8][2] > best1) { best1 = C[n8][2]; bi1 = code; }
            if (C[n8][3] > best1) { best1 = C[n8][3]; bi1 = code + 1; }
        }
    }

    // cross-lane reduce among the 4 lanes sharing each row
#pragma unroll
    for (int off = 1; off <= 2; off <<= 1) {
        float v0 = __shfl_xor_sync(0xFFFFFFFFu, best0, off);
        int   i0 = __shfl_xor_sync(0xFFFFFFFFu, bi0,   off);
        if (v0 > best0 || (v0 == best0 && i0 < bi0)) { best0 = v0; bi0 = i0; }
        float v1 = __shfl_xor_sync(0xFFFFFFFFu, best1, off);
        int   i1 = __shfl_xor_sync(0xFFFFFFFFu, bi1,   off);
        if (v1 > best1 || (v1 == best1 && i1 < bi1)) { best1 = v1; bi1 = i1; }
    }
    if ((lane & 3) == 0) {
        const int r = lane >> 2;
        out[rowBase + wid * 16 + r]     = (float)bi0;
        out[rowBase + wid * 16 + r + 8] = (float)bi1;
    }
}

// ---------------------------------------------------------------------------
// Harness entry
// ---------------------------------------------------------------------------
extern "C" void kernel_launch(void* const* d_in, const int* in_sizes, int n_in,
                              void* d_out, int out_size) {
    const float* inp = (const float*)d_in[0];
    const float* cb  = (const float*)d_in[1];
    if (in_sizes[0] == NUM_CODES * DIM && in_sizes[1] != NUM_CODES * DIM) {
        const float* tmp = inp; inp = cb; cb = tmp;
    }
    float* out = (float*)d_out;

    cudaFuncSetAttribute(vq_mma_kernel,
                         cudaFuncAttributeMaxDynamicSharedMemorySize, SM_ALLOC);
    vq_prep<<<16, 256>>>(cb);
    vq_mma_kernel<<<N_ROWS / M_TILE, THREADS, SM_ALLOC>>>(inp, out);
}

// round 12
// speedup vs baseline: 1.1664x; 1.0077x over previous
#include <cuda_runtime.h>
#include <cuda_bf16.h>
#include <cstdint>

// VQ nearest-codebook search via warp-level mma.sync (HMMA, baseline PTX —
// harness targets compute_103, no tcgen05/'a' features available).
//   inputs [16,64,64,64] NCHW fp32, codebook [1024,64] fp32
//   out[n] (as float32) = argmin_k ||x_n - e_k||^2
//                       = argmax_k ( x_n.e_k - 0.5||e_k||^2 )
// bf16 triple-split x = b0+b1+b2; 6 accumulating bf16 MMA passes into fp32.
// R12: reclaim dead A-smem as a 4-stage B ring (cp.async 3 chunks ahead);
// one barrier per chunk; MMA phase starts immediately at chunk top.
// HMMA.16816 measured rt~8/SMSP => main-kernel floor ~94us; target duty 80%.

#define NUM_CODES 1024
#define DIM       64
#define M_TILE    128
#define N_CHUNK   64
#define CHUNKS    16
#define THREADS   256
#define N_ROWS    65536
#define HW        4096
#define ATILE     16384            // [128 rows][64 bf16] A tile (prologue only)
#define BTILE     8192             // [64 codes][64 bf16] B tile
#define STAGES    4

// smem layout (relative to 1024-aligned base)
#define SM_H      0                          // 1024 floats (-0.5||e||^2)
#define SM_RING   4096                       // 4 stages x 3 comps x 8 KB = 96 KB
#define SM_A      SM_RING                    // A built here, freed after Af load
#define SM_TOTAL  (SM_RING + STAGES * 3 * BTILE)   // 102400
#define SM_ALLOC  (SM_TOTAL + 1024)

__device__ float g_h[NUM_CODES];                       // -0.5*||e_k||^2
__device__ __align__(16) unsigned char g_bsplit[3 * CHUNKS * BTILE];

#define SW128(o) ((o) ^ (((o) >> 3) & 0x70))

__device__ __forceinline__ uint32_t smem_u32(const void* p) {
    uint32_t a;
    asm("{ .reg .u64 t; cvta.to.shared.u64 t, %1; cvt.u32.u64 %0, t; }"
        : "=r"(a) : "l"(p));
    return a;
}

#define LDSM_X4(r, a) \
    asm volatile("ldmatrix.sync.aligned.m8n8.x4.shared.b16 {%0,%1,%2,%3}, [%4];" \
        : "=r"((r)[0]), "=r"((r)[1]), "=r"((r)[2]), "=r"((r)[3]) : "r"(a))
#define MMA(c, A, B) \
    asm volatile("mma.sync.aligned.m16n8k16.row.col.f32.bf16.bf16.f32 " \
        "{%0,%1,%2,%3}, {%4,%5,%6,%7}, {%8,%9}, {%0,%1,%2,%3};" \
        : "+f"((c)[0]), "+f"((c)[1]), "+f"((c)[2]), "+f"((c)[3]) \
        : "r"((A)[0]), "r"((A)[1]), "r"((A)[2]), "r"((A)[3]), \
          "r"((B)[0]), "r"((B)[1]))
#define CP16(dst, src) \
    asm volatile("cp.async.cg.shared.global [%0], [%1], 16;" :: "r"(dst), "l"(src))
#define CP_COMMIT() asm volatile("cp.async.commit_group;" ::: "memory")
#define CP_WAIT(n)  asm volatile("cp.async.wait_group %0;" :: "n"(n) : "memory")

__device__ __forceinline__ uint32_t pack_bf16(__nv_bfloat16 lo, __nv_bfloat16 hi) {
    return ((uint32_t)__bfloat16_as_ushort(hi) << 16) | __bfloat16_as_ushort(lo);
}
__device__ __forceinline__ void split3(float x, __nv_bfloat16& c0,
                                       __nv_bfloat16& c1, __nv_bfloat16& c2) {
    c0 = __float2bfloat16(x);
    float r0 = x - __bfloat162float(c0);
    c1 = __float2bfloat16(r0);
    float r1 = r0 - __bfloat162float(c1);
    c2 = __float2bfloat16(r1);
}

// ---------------------------------------------------------------------------
// Prep: split codebook into 3 bf16 comps, pre-swizzled [64-code] tiles; norms.
// ---------------------------------------------------------------------------
__global__ void vq_prep(const float* __restrict__ cb) {
    int g = blockIdx.x * blockDim.x + threadIdx.x;   // 0..4095
    int j = g >> 2;                                  // code
    int q = g & 3;                                   // dim quarter
    int chunk = j >> 6, jr = j & 63;
    float nrm = 0.f;
#pragma unroll
    for (int i = 0; i < 8; ++i) {
        int dp = q * 8 + i;                          // dim pair
        float x0 = cb[(size_t)j * DIM + 2 * dp];
        float x1 = cb[(size_t)j * DIM + 2 * dp + 1];
        nrm = fmaf(x0, x0, nrm);
        nrm = fmaf(x1, x1, nrm);
        __nv_bfloat16 a0, a1, a2, b0, b1, b2;
        split3(x0, a0, a1, a2);
        split3(x1, b0, b1, b2);
        uint32_t sw = SW128((uint32_t)(jr * 128 + dp * 4));
        *(uint32_t*)&g_bsplit[(0 * CHUNKS + chunk) * BTILE + sw] = pack_bf16(a0, b0);
        *(uint32_t*)&g_bsplit[(1 * CHUNKS + chunk) * BTILE + sw] = pack_bf16(a1, b1);
        *(uint32_t*)&g_bsplit[(2 * CHUNKS + chunk) * BTILE + sw] = pack_bf16(a2, b2);
    }
    nrm += __shfl_xor_sync(0xFFFFFFFFu, nrm, 1);
    nrm += __shfl_xor_sync(0xFFFFFFFFu, nrm, 2);
    if (q == 0) g_h[j] = -0.5f * nrm;
}

// ---------------------------------------------------------------------------
// Main kernel
// ---------------------------------------------------------------------------
__device__ __forceinline__ void cp_chunk(uint32_t sb, int c, int stage, int tid) {
#pragma unroll
    for (int t = 0; t < 3; ++t) {
#pragma unroll
        for (int i = 0; i < 2; ++i) {       // 512 float4 per 8KB tile
            int idx = i * THREADS + tid;
            uint32_t dst = sb + SM_RING + (stage * 3 + t) * BTILE + idx * 16;
            const unsigned char* src = &g_bsplit[(t * CHUNKS + c) * BTILE + idx * 16];
            CP16(dst, src);
        }
    }
}

__global__ __launch_bounds__(THREADS, 2)
void vq_mma_kernel(const float* __restrict__ in, float* __restrict__ out) {
    extern __shared__ char smraw[];
    const uint32_t sbr = smem_u32(smraw);
    const uint32_t sb  = (sbr + 1023u) & ~1023u;    // 1K-align for swizzle
    char* sm = smraw + (sb - sbr);

    const int tid  = threadIdx.x;
    const int wid  = tid >> 5;
    const int lane = tid & 31;

    // -0.5||e||^2 -> smem
    float* sh = (float*)(sm + SM_H);
    for (int i = tid; i < NUM_CODES; i += THREADS) sh[i] = g_h[i];

    // build A (in ring space; freed after Af load): 128 rows x 64 ch
    const int rowBase = blockIdx.x * M_TILE;
    const int b   = rowBase >> 12;
    const int hw0 = rowBase & (HW - 1);
    const float* xin = in + ((size_t)b * DIM * HW) + hw0;
#pragma unroll
    for (int i = 0; i < 16; ++i) {
        int idx = i * THREADS + tid;
        int r = idx & 127, dp = idx >> 7;
        float x0 = xin[(size_t)(2 * dp) * HW + r];
        float x1 = xin[(size_t)(2 * dp + 1) * HW + r];
        __nv_bfloat16 a0, a1, a2, b0, b1, b2;
        split3(x0, a0, a1, a2);
        split3(x1, b0, b1, b2);
        uint32_t sw = SW128((uint32_t)(r * 128 + dp * 4));
        *(uint32_t*)(sm + SM_A + 0 * ATILE + sw) = pack_bf16(a0, b0);
        *(uint32_t*)(sm + SM_A + 1 * ATILE + sw) = pack_bf16(a1, b1);
        *(uint32_t*)(sm + SM_A + 2 * ATILE + sw) = pack_bf16(a2, b2);
    }
    __syncthreads();      // A ready

    // A fragments in registers: warp w = rows w*16..w*16+15.  48 regs.
    uint32_t Af[3][4][4];
    {
        const int arow = wid * 16 + (lane & 15);
        const uint32_t colb = (uint32_t)((lane >> 4) * 16);
#pragma unroll
        for (int t = 0; t < 3; ++t)
#pragma unroll
            for (int ks = 0; ks < 4; ++ks) {
                uint32_t off = (uint32_t)(arow * 128)
                             + ((colb + ks * 32) ^ ((uint32_t)(arow & 7) << 4));
                LDSM_X4(Af[t][ks], sb + SM_A + t * ATILE + off);
            }
    }
    __syncthreads();      // all Af loads done; ring space free for cp

    // prefetch chunks 0..2 into stages 0..2 (one group each)
    cp_chunk(sb, 0, 0, tid); CP_COMMIT();
    cp_chunk(sb, 1, 1, tid); CP_COMMIT();
    cp_chunk(sb, 2, 2, tid); CP_COMMIT();
    CP_WAIT(2);           // chunk 0 arrived
    __syncthreads();      // visible to all warps

    // B ldmatrix.x4 lane geometry
    const int r7 = lane & 7;
    const int ms = (lane >> 3) & 1;
    const int j2 = lane >> 4;
    const uint32_t blane = (uint32_t)(j2 * 1024 + r7 * 128);
    const int colOff = 2 * (lane & 3);

    float best0 = -3.402823466e38f, best1 = -3.402823466e38f;
    int   bi0 = 0, bi1 = 0;

    for (int c = 0; c < CHUNKS; ++c) {
        const int stage = c & (STAGES - 1);
        // issue cp for chunk c+3 into stage (c+3)&3 == (c-1)&3, whose reads
        // all finished before the barrier at the end of chunk c-1.
        if (c + 3 < CHUNKS) { cp_chunk(sb, c + 3, (c + 3) & (STAGES - 1), tid); CP_COMMIT(); }

        // C init = -0.5||e||^2
        float C[8][4];
#pragma unroll
        for (int n8 = 0; n8 < 8; ++n8) {
            float2 h2 = *(const float2*)&sh[c * N_CHUNK + n8 * 8 + colOff];
            C[n8][0] = h2.x; C[n8][1] = h2.y;
            C[n8][2] = h2.x; C[n8][3] = h2.y;
        }

#pragma unroll
        for (int ks = 0; ks < 4; ++ks) {
            const uint32_t kc = (uint32_t)((ks * 32 + ms * 16) ^ (r7 << 4));
#pragma unroll
            for (int t = 0; t < 3; ++t) {      // B component
                const uint32_t bbase = sb + SM_RING + (stage * 3 + t) * BTILE
                                     + blane + kc;
                uint32_t Bt[4][4];             // 8 n8 frags (2 per LDSM_X4)
#pragma unroll
                for (int n16 = 0; n16 < 4; ++n16)
                    LDSM_X4(Bt[n16], bbase + (uint32_t)(n16 * 2048));
#pragma unroll
                for (int at = 0; at < 3 - t; ++at) {
#pragma unroll
                    for (int n16 = 0; n16 < 4; ++n16) {
                        MMA(C[2 * n16],     Af[at][ks], &Bt[n16][0]);
                        MMA(C[2 * n16 + 1], Af[at][ks], &Bt[n16][2]);
                    }
                }
            }
        }

        // epilogue: argmax over this chunk (codes ascending -> first-min tie)
#pragma unroll
        for (int n8 = 0; n8 < 8; ++n8) {
            const int code = c * N_CHUNK + n8 * 8 + colOff;
            if (C[n8][0] > best0) { best0 = C[n8][0]; bi0 = code; }
            if (C[n8][1] > best0) { best0 = C[n8][1]; bi0 = code + 1; }
            if (C[n8][2] > best1) { best1 = C[n8][2]; bi1 = code; }
            if (C[n8][3] > best1) { best1 = C[n8][3]; bi1 = code + 1; }
        }

        // end-of-chunk: ensure chunk c+1 arrived, then one barrier that both
        // publishes c+1's data and retires this stage for reuse at c+4.
        if (c + 1 < CHUNKS) {
            if (c + 3 < CHUNKS) { CP_WAIT(2); } else { CP_WAIT(0); }
            __syncthreads();
        }
    }

    // cross-lane reduce among the 4 lanes sharing each row
#pragma unroll
    for (int off = 1; off <= 2; off <<= 1) {
        float v0 = __shfl_xor_sync(0xFFFFFFFFu, best0, off);
        int   i0 = __shfl_xor_sync(0xFFFFFFFFu, bi0,   off);
        if (v0 > best0 || (v0 == best0 && i0 < bi0)) { best0 = v0; bi0 = i0; }
        float v1 = __shfl_xor_sync(0xFFFFFFFFu, best1, off);
        int   i1 = __shfl_xor_sync(0xFFFFFFFFu, bi1,   off);
        if (v1 > best1 || (v1 == best1 && i1 < bi1)) { best1 = v1; bi1 = i1; }
    }
    if ((lane & 3) == 0) {
        const int r = lane >> 2;
        out[rowBase + wid * 16 + r]     = (float)bi0;
        out[rowBase + wid * 16 + r + 8] = (float)bi1;
    }
}

// ---------------------------------------------------------------------------
// Harness entry
// ---------------------------------------------------------------------------
extern "C" void kernel_launch(void* const* d_in, const int* in_sizes, int n_in,
                              void* d_out, int out_size) {
    const float* inp = (const float*)d_in[0];
    const float* cb  = (const float*)d_in[1];
    if (in_sizes[0] == NUM_CODES * DIM && in_sizes[1] != NUM_CODES * DIM) {
        const float* tmp = inp; inp = cb; cb = tmp;
    }
    float* out = (float*)d_out;

    cudaFuncSetAttribute(vq_mma_kernel,
                         cudaFuncAttributeMaxDynamicSharedMemorySize, SM_ALLOC);
    vq_prep<<<16, 256>>>(cb);
    vq_mma_kernel<<<N_ROWS / M_TILE, THREADS, SM_ALLOC>>>(inp, out);
}

// round 13
// speedup vs baseline: 1.6092x; 1.3796x over previous
#include <cuda_runtime.h>
#include <cuda_fp16.h>
#include <cstdint>

// VQ nearest-codebook search via warp-level mma.sync (HMMA, baseline PTX —
// harness targets compute_103, no tcgen05/'a' features available).
//   inputs [16,64,64,64] NCHW fp32, codebook [1024,64] fp32
//   out[n] (as float32) = argmin_k ||x_n - e_k||^2
//                       = argmax_k ( x_n.e_k - 0.5||e_k||^2 )
// R13: fp16 pair-split x ~= h0+h1, e ~= e0+e1 (22 mantissa bits each);
// dot = FULL product (h0+h1).(e0+e1) via 4 accumulating fp16 MMA passes
// (error = representation only, ~2^-22 rel). 33% fewer MMAs than bf16-6.

#define NUM_CODES 1024
#define DIM       64
#define M_TILE    128
#define N_CHUNK   64
#define CHUNKS    16
#define THREADS   256
#define N_ROWS    65536
#define HW        4096
#define ATILE     16384            // [128 rows][64 fp16] A tile (prologue only)
#define BTILE     8192             // [64 codes][64 fp16] B tile
#define STAGES    4
#define COMPS     2

// smem layout (relative to 1024-aligned base)
#define SM_H      0                          // 1024 floats (-0.5||e||^2)
#define SM_RING   4096                       // 4 stages x 2 comps x 8 KB = 64 KB
#define SM_A      SM_RING                    // A built here, freed after Af load
#define SM_TOTAL  (SM_RING + STAGES * COMPS * BTILE)   // 69632
#define SM_ALLOC  (SM_TOTAL + 1024)

__device__ float g_h[NUM_CODES];                       // -0.5*||e_k||^2
__device__ __align__(16) unsigned char g_bsplit[COMPS * CHUNKS * BTILE];

#define SW128(o) ((o) ^ (((o) >> 3) & 0x70))

__device__ __forceinline__ uint32_t smem_u32(const void* p) {
    uint32_t a;
    asm("{ .reg .u64 t; cvta.to.shared.u64 t, %1; cvt.u32.u64 %0, t; }"
        : "=r"(a) : "l"(p));
    return a;
}

#define LDSM_X4(r, a) \
    asm volatile("ldmatrix.sync.aligned.m8n8.x4.shared.b16 {%0,%1,%2,%3}, [%4];" \
        : "=r"((r)[0]), "=r"((r)[1]), "=r"((r)[2]), "=r"((r)[3]) : "r"(a))
#define MMA(c, A, B) \
    asm volatile("mma.sync.aligned.m16n8k16.row.col.f32.f16.f16.f32 " \
        "{%0,%1,%2,%3}, {%4,%5,%6,%7}, {%8,%9}, {%0,%1,%2,%3};" \
        : "+f"((c)[0]), "+f"((c)[1]), "+f"((c)[2]), "+f"((c)[3]) \
        : "r"((A)[0]), "r"((A)[1]), "r"((A)[2]), "r"((A)[3]), \
          "r"((B)[0]), "r"((B)[1]))
#define CP16(dst, src) \
    asm volatile("cp.async.cg.shared.global [%0], [%1], 16;" :: "r"(dst), "l"(src))
#define CP_COMMIT() asm volatile("cp.async.commit_group;" ::: "memory")
#define CP_WAIT(n)  asm volatile("cp.async.wait_group %0;" :: "n"(n) : "memory")

__device__ __forceinline__ uint32_t pack_h2(__half lo, __half hi) {
    return ((uint32_t)__half_as_ushort(hi) << 16) | __half_as_ushort(lo);
}
__device__ __forceinline__ void split2(float x, __half& c0, __half& c1) {
    c0 = __float2half_rn(x);
    c1 = __float2half_rn(x - __half2float(c0));
}

// ---------------------------------------------------------------------------
// Prep: split codebook into 2 fp16 comps, pre-swizzled [64-code] tiles; norms.
// ---------------------------------------------------------------------------
__global__ void vq_prep(const float* __restrict__ cb) {
    int g = blockIdx.x * blockDim.x + threadIdx.x;   // 0..4095
    int j = g >> 2;                                  // code
    int q = g & 3;                                   // dim quarter
    int chunk = j >> 6, jr = j & 63;
    float nrm = 0.f;
#pragma unroll
    for (int i = 0; i < 8; ++i) {
        int dp = q * 8 + i;                          // dim pair
        float x0 = cb[(size_t)j * DIM + 2 * dp];
        float x1 = cb[(size_t)j * DIM + 2 * dp + 1];
        nrm = fmaf(x0, x0, nrm);
        nrm = fmaf(x1, x1, nrm);
        __half a0, a1, b0, b1;
        split2(x0, a0, a1);
        split2(x1, b0, b1);
        uint32_t sw = SW128((uint32_t)(jr * 128 + dp * 4));
        *(uint32_t*)&g_bsplit[(0 * CHUNKS + chunk) * BTILE + sw] = pack_h2(a0, b0);
        *(uint32_t*)&g_bsplit[(1 * CHUNKS + chunk) * BTILE + sw] = pack_h2(a1, b1);
    }
    nrm += __shfl_xor_sync(0xFFFFFFFFu, nrm, 1);
    nrm += __shfl_xor_sync(0xFFFFFFFFu, nrm, 2);
    if (q == 0) g_h[j] = -0.5f * nrm;
}

// ---------------------------------------------------------------------------
// Main kernel
// ---------------------------------------------------------------------------
__device__ __forceinline__ void cp_chunk(uint32_t sb, int c, int stage, int tid) {
#pragma unroll
    for (int t = 0; t < COMPS; ++t) {
#pragma unroll
        for (int i = 0; i < 2; ++i) {       // 512 float4 per 8KB tile
            int idx = i * THREADS + tid;
            uint32_t dst = sb + SM_RING + (stage * COMPS + t) * BTILE + idx * 16;
            const unsigned char* src = &g_bsplit[(t * CHUNKS + c) * BTILE + idx * 16];
            CP16(dst, src);
        }
    }
}

__global__ __launch_bounds__(THREADS, 2)
void vq_mma_kernel(const float* __restrict__ in, float* __restrict__ out) {
    extern __shared__ char smraw[];
    const uint32_t sbr = smem_u32(smraw);
    const uint32_t sb  = (sbr + 1023u) & ~1023u;    // 1K-align for swizzle
    char* sm = smraw + (sb - sbr);

    const int tid  = threadIdx.x;
    const int wid  = tid >> 5;
    const int lane = tid & 31;

    // -0.5||e||^2 -> smem
    float* sh = (float*)(sm + SM_H);
    for (int i = tid; i < NUM_CODES; i += THREADS) sh[i] = g_h[i];

    // build A (in ring space; freed after Af load): 128 rows x 64 ch
    const int rowBase = blockIdx.x * M_TILE;
    const int b   = rowBase >> 12;
    const int hw0 = rowBase & (HW - 1);
    const float* xin = in + ((size_t)b * DIM * HW) + hw0;
#pragma unroll
    for (int i = 0; i < 16; ++i) {
        int idx = i * THREADS + tid;
        int r = idx & 127, dp = idx >> 7;
        float x0 = xin[(size_t)(2 * dp) * HW + r];
        float x1 = xin[(size_t)(2 * dp + 1) * HW + r];
        __half a0, a1, b0, b1;
        split2(x0, a0, a1);
        split2(x1, b0, b1);
        uint32_t sw = SW128((uint32_t)(r * 128 + dp * 4));
        *(uint32_t*)(sm + SM_A + 0 * ATILE + sw) = pack_h2(a0, b0);
        *(uint32_t*)(sm + SM_A + 1 * ATILE + sw) = pack_h2(a1, b1);
    }
    __syncthreads();      // A ready

    // A fragments in registers: warp w = rows w*16..w*16+15.  32 regs.
    uint32_t Af[COMPS][4][4];
    {
        const int arow = wid * 16 + (lane & 15);
        const uint32_t colb = (uint32_t)((lane >> 4) * 16);
#pragma unroll
        for (int t = 0; t < COMPS; ++t)
#pragma unroll
            for (int ks = 0; ks < 4; ++ks) {
                uint32_t off = (uint32_t)(arow * 128)
                             + ((colb + ks * 32) ^ ((uint32_t)(arow & 7) << 4));
                LDSM_X4(Af[t][ks], sb + SM_A + t * ATILE + off);
            }
    }
    __syncthreads();      // all Af loads done; ring space free for cp

    // prefetch chunks 0..2 into stages 0..2 (one group each)
    cp_chunk(sb, 0, 0, tid); CP_COMMIT();
    cp_chunk(sb, 1, 1, tid); CP_COMMIT();
    cp_chunk(sb, 2, 2, tid); CP_COMMIT();
    CP_WAIT(2);           // chunk 0 arrived
    __syncthreads();      // visible to all warps

    // B ldmatrix.x4 lane geometry
    const int r7 = lane & 7;
    const int ms = (lane >> 3) & 1;
    const int j2 = lane >> 4;
    const uint32_t blane = (uint32_t)(j2 * 1024 + r7 * 128);
    const int colOff = 2 * (lane & 3);

    float best0 = -3.402823466e38f, best1 = -3.402823466e38f;
    int   bi0 = 0, bi1 = 0;

    for (int c = 0; c < CHUNKS; ++c) {
        const int stage = c & (STAGES - 1);
        // issue cp for chunk c+3 into stage (c+3)&3 == (c-1)&3 (retired at
        // the barrier that ended chunk c-1).
        if (c + 3 < CHUNKS) { cp_chunk(sb, c + 3, (c + 3) & (STAGES - 1), tid); CP_COMMIT(); }

        // C init = -0.5||e||^2
        float C[8][4];
#pragma unroll
        for (int n8 = 0; n8 < 8; ++n8) {
            float2 h2 = *(const float2*)&sh[c * N_CHUNK + n8 * 8 + colOff];
            C[n8][0] = h2.x; C[n8][1] = h2.y;
            C[n8][2] = h2.x; C[n8][3] = h2.y;
        }

#pragma unroll
        for (int ks = 0; ks < 4; ++ks) {
            const uint32_t kc = (uint32_t)((ks * 32 + ms * 16) ^ (r7 << 4));
#pragma unroll
            for (int t = 0; t < COMPS; ++t) {  // B component
                const uint32_t bbase = sb + SM_RING + (stage * COMPS + t) * BTILE
                                     + blane + kc;
                uint32_t Bt[4][4];             // 8 n8 frags (2 per LDSM_X4)
#pragma unroll
                for (int n16 = 0; n16 < 4; ++n16)
                    LDSM_X4(Bt[n16], bbase + (uint32_t)(n16 * 2048));
                // full product: both A comps against this B comp
#pragma unroll
                for (int at = 0; at < COMPS; ++at) {
#pragma unroll
                    for (int n16 = 0; n16 < 4; ++n16) {
                        MMA(C[2 * n16],     Af[at][ks], &Bt[n16][0]);
                        MMA(C[2 * n16 + 1], Af[at][ks], &Bt[n16][2]);
                    }
                }
            }
        }

        // epilogue: argmax over this chunk (codes ascending -> first-min tie)
#pragma unroll
        for (int n8 = 0; n8 < 8; ++n8) {
            const int code = c * N_CHUNK + n8 * 8 + colOff;
            if (C[n8][0] > best0) { best0 = C[n8][0]; bi0 = code; }
            if (C[n8][1] > best0) { best0 = C[n8][1]; bi0 = code + 1; }
            if (C[n8][2] > best1) { best1 = C[n8][2]; bi1 = code; }
            if (C[n8][3] > best1) { best1 = C[n8][3]; bi1 = code + 1; }
        }

        // end-of-chunk: ensure chunk c+1 arrived; one barrier publishes it
        // and retires this stage for reuse at c+4.
        if (c + 1 < CHUNKS) {
            if (c + 3 < CHUNKS) { CP_WAIT(2); } else { CP_WAIT(0); }
            __syncthreads();
        }
    }

    // cross-lane reduce among the 4 lanes sharing each row
#pragma unroll
    for (int off = 1; off <= 2; off <<= 1) {
        float v0 = __shfl_xor_sync(0xFFFFFFFFu, best0, off);
        int   i0 = __shfl_xor_sync(0xFFFFFFFFu, bi0,   off);
        if (v0 > best0 || (v0 == best0 && i0 < bi0)) { best0 = v0; bi0 = i0; }
        float v1 = __shfl_xor_sync(0xFFFFFFFFu, best1, off);
        int   i1 = __shfl_xor_sync(0xFFFFFFFFu, bi1,   off);
        if (v1 > best1 || (v1 == best1 && i1 < bi1)) { best1 = v1; bi1 = i1; }
    }
    if ((lane & 3) == 0) {
        const int r = lane >> 2;
        out[rowBase + wid * 16 + r]     = (float)bi0;
        out[rowBase + wid * 16 + r + 8] = (float)bi1;
    }
}

// ---------------------------------------------------------------------------
// Harness entry
// ---------------------------------------------------------------------------
extern "C" void kernel_launch(void* const* d_in, const int* in_sizes, int n_in,
                              void* d_out, int out_size) {
    const float* inp = (const float*)d_in[0];
    const float* cb  = (const float*)d_in[1];
    if (in_sizes[0] == NUM_CODES * DIM && in_sizes[1] != NUM_CODES * DIM) {
        const float* tmp = inp; inp = cb; cb = tmp;
    }
    float* out = (float*)d_out;

    cudaFuncSetAttribute(vq_mma_kernel,
                         cudaFuncAttributeMaxDynamicSharedMemorySize, SM_ALLOC);
    vq_prep<<<16, 256>>>(cb);
    vq_mma_kernel<<<N_ROWS / M_TILE, THREADS, SM_ALLOC>>>(inp, out);
}

// round 14
// speedup vs baseline: 1.9431x; 1.2075x over previous
#include <cuda_runtime.h>
#include <cuda_fp16.h>
#include <cstdint>

// VQ nearest-codebook search via warp-level mma.sync (HMMA, baseline PTX —
// harness targets compute_103, no tcgen05/'a' features available).
//   inputs [16,64,64,64] NCHW fp32, codebook [1024,64] fp32
//   out[n] (as float32) = argmin_k ||x_n - e_k||^2
//                       = argmax_k ( x_n.e_k - 0.5||e_k||^2 )
// R14: fp16 pair-split, 3 MMA passes (h0e0 + h1e0 + h0e1; the h1e1 term is
// ~2^-22 and dropped). 25% fewer MMAs than R13, same exact-fp32 norms.

#define NUM_CODES 1024
#define DIM       64
#define M_TILE    128
#define N_CHUNK   64
#define CHUNKS    16
#define THREADS   256
#define N_ROWS    65536
#define HW        4096
#define ATILE     16384            // [128 rows][64 fp16] A tile (prologue only)
#define BTILE     8192             // [64 codes][64 fp16] B tile
#define STAGES    4
#define COMPS     2

// smem layout (relative to 1024-aligned base)
#define SM_H      0                          // 1024 floats (-0.5||e||^2)
#define SM_RING   4096                       // 4 stages x 2 comps x 8 KB = 64 KB
#define SM_A      SM_RING                    // A built here, freed after Af load
#define SM_TOTAL  (SM_RING + STAGES * COMPS * BTILE)   // 69632
#define SM_ALLOC  (SM_TOTAL + 1024)

__device__ float g_h[NUM_CODES];                       // -0.5*||e_k||^2
__device__ __align__(16) unsigned char g_bsplit[COMPS * CHUNKS * BTILE];

#define SW128(o) ((o) ^ (((o) >> 3) & 0x70))

__device__ __forceinline__ uint32_t smem_u32(const void* p) {
    uint32_t a;
    asm("{ .reg .u64 t; cvta.to.shared.u64 t, %1; cvt.u32.u64 %0, t; }"
        : "=r"(a) : "l"(p));
    return a;
}

#define LDSM_X4(r, a) \
    asm volatile("ldmatrix.sync.aligned.m8n8.x4.shared.b16 {%0,%1,%2,%3}, [%4];" \
        : "=r"((r)[0]), "=r"((r)[1]), "=r"((r)[2]), "=r"((r)[3]) : "r"(a))
#define MMA(c, A, B) \
    asm volatile("mma.sync.aligned.m16n8k16.row.col.f32.f16.f16.f32 " \
        "{%0,%1,%2,%3}, {%4,%5,%6,%7}, {%8,%9}, {%0,%1,%2,%3};" \
        : "+f"((c)[0]), "+f"((c)[1]), "+f"((c)[2]), "+f"((c)[3]) \
        : "r"((A)[0]), "r"((A)[1]), "r"((A)[2]), "r"((A)[3]), \
          "r"((B)[0]), "r"((B)[1]))
#define CP16(dst, src) \
    asm volatile("cp.async.cg.shared.global [%0], [%1], 16;" :: "r"(dst), "l"(src))
#define CP_COMMIT() asm volatile("cp.async.commit_group;" ::: "memory")
#define CP_WAIT(n)  asm volatile("cp.async.wait_group %0;" :: "n"(n) : "memory")

__device__ __forceinline__ uint32_t pack_h2(__half lo, __half hi) {
    return ((uint32_t)__half_as_ushort(hi) << 16) | __half_as_ushort(lo);
}
__device__ __forceinline__ void split2(float x, __half& c0, __half& c1) {
    c0 = __float2half_rn(x);
    c1 = __float2half_rn(x - __half2float(c0));
}

// ---------------------------------------------------------------------------
// Prep: split codebook into 2 fp16 comps, pre-swizzled [64-code] tiles; norms.
// ---------------------------------------------------------------------------
__global__ void vq_prep(const float* __restrict__ cb) {
    int g = blockIdx.x * blockDim.x + threadIdx.x;   // 0..4095
    int j = g >> 2;                                  // code
    int q = g & 3;                                   // dim quarter
    int chunk = j >> 6, jr = j & 63;
    float nrm = 0.f;
#pragma unroll
    for (int i = 0; i < 8; ++i) {
        int dp = q * 8 + i;                          // dim pair
        float x0 = cb[(size_t)j * DIM + 2 * dp];
        float x1 = cb[(size_t)j * DIM + 2 * dp + 1];
        nrm = fmaf(x0, x0, nrm);
        nrm = fmaf(x1, x1, nrm);
        __half a0, a1, b0, b1;
        split2(x0, a0, a1);
        split2(x1, b0, b1);
        uint32_t sw = SW128((uint32_t)(jr * 128 + dp * 4));
        *(uint32_t*)&g_bsplit[(0 * CHUNKS + chunk) * BTILE + sw] = pack_h2(a0, b0);
        *(uint32_t*)&g_bsplit[(1 * CHUNKS + chunk) * BTILE + sw] = pack_h2(a1, b1);
    }
    nrm += __shfl_xor_sync(0xFFFFFFFFu, nrm, 1);
    nrm += __shfl_xor_sync(0xFFFFFFFFu, nrm, 2);
    if (q == 0) g_h[j] = -0.5f * nrm;
}

// ---------------------------------------------------------------------------
// Main kernel
// ---------------------------------------------------------------------------
__device__ __forceinline__ void cp_chunk(uint32_t sb, int c, int stage, int tid) {
#pragma unroll
    for (int t = 0; t < COMPS; ++t) {
#pragma unroll
        for (int i = 0; i < 2; ++i) {       // 512 float4 per 8KB tile
            int idx = i * THREADS + tid;
            uint32_t dst = sb + SM_RING + (stage * COMPS + t) * BTILE + idx * 16;
            const unsigned char* src = &g_bsplit[(t * CHUNKS + c) * BTILE + idx * 16];
            CP16(dst, src);
        }
    }
}

__global__ __launch_bounds__(THREADS, 2)
void vq_mma_kernel(const float* __restrict__ in, float* __restrict__ out) {
    extern __shared__ char smraw[];
    const uint32_t sbr = smem_u32(smraw);
    const uint32_t sb  = (sbr + 1023u) & ~1023u;    // 1K-align for swizzle
    char* sm = smraw + (sb - sbr);

    const int tid  = threadIdx.x;
    const int wid  = tid >> 5;
    const int lane = tid & 31;

    // -0.5||e||^2 -> smem
    float* sh = (float*)(sm + SM_H);
    for (int i = tid; i < NUM_CODES; i += THREADS) sh[i] = g_h[i];

    // build A (in ring space; freed after Af load): 128 rows x 64 ch
    const int rowBase = blockIdx.x * M_TILE;
    const int b   = rowBase >> 12;
    const int hw0 = rowBase & (HW - 1);
    const float* xin = in + ((size_t)b * DIM * HW) + hw0;
#pragma unroll
    for (int i = 0; i < 16; ++i) {
        int idx = i * THREADS + tid;
        int r = idx & 127, dp = idx >> 7;
        float x0 = xin[(size_t)(2 * dp) * HW + r];
        float x1 = xin[(size_t)(2 * dp + 1) * HW + r];
        __half a0, a1, b0, b1;
        split2(x0, a0, a1);
        split2(x1, b0, b1);
        uint32_t sw = SW128((uint32_t)(r * 128 + dp * 4));
        *(uint32_t*)(sm + SM_A + 0 * ATILE + sw) = pack_h2(a0, b0);
        *(uint32_t*)(sm + SM_A + 1 * ATILE + sw) = pack_h2(a1, b1);
    }
    __syncthreads();      // A ready

    // A fragments in registers: warp w = rows w*16..w*16+15.  32 regs.
    uint32_t Af[COMPS][4][4];
    {
        const int arow = wid * 16 + (lane & 15);
        const uint32_t colb = (uint32_t)((lane >> 4) * 16);
#pragma unroll
        for (int t = 0; t < COMPS; ++t)
#pragma unroll
            for (int ks = 0; ks < 4; ++ks) {
                uint32_t off = (uint32_t)(arow * 128)
                             + ((colb + ks * 32) ^ ((uint32_t)(arow & 7) << 4));
                LDSM_X4(Af[t][ks], sb + SM_A + t * ATILE + off);
            }
    }
    __syncthreads();      // all Af loads done; ring space free for cp

    // prefetch chunks 0..2 into stages 0..2 (one group each)
    cp_chunk(sb, 0, 0, tid); CP_COMMIT();
    cp_chunk(sb, 1, 1, tid); CP_COMMIT();
    cp_chunk(sb, 2, 2, tid); CP_COMMIT();
    CP_WAIT(2);           // chunk 0 arrived
    __syncthreads();      // visible to all warps

    // B ldmatrix.x4 lane geometry
    const int r7 = lane & 7;
    const int ms = (lane >> 3) & 1;
    const int j2 = lane >> 4;
    const uint32_t blane = (uint32_t)(j2 * 1024 + r7 * 128);
    const int colOff = 2 * (lane & 3);

    float best0 = -3.402823466e38f, best1 = -3.402823466e38f;
    int   bi0 = 0, bi1 = 0;

    for (int c = 0; c < CHUNKS; ++c) {
        const int stage = c & (STAGES - 1);
        // issue cp for chunk c+3 into stage (c+3)&3 == (c-1)&3 (retired at
        // the barrier that ended chunk c-1).
        if (c + 3 < CHUNKS) { cp_chunk(sb, c + 3, (c + 3) & (STAGES - 1), tid); CP_COMMIT(); }

        // C init = -0.5||e||^2
        float C[8][4];
#pragma unroll
        for (int n8 = 0; n8 < 8; ++n8) {
            float2 h2 = *(const float2*)&sh[c * N_CHUNK + n8 * 8 + colOff];
            C[n8][0] = h2.x; C[n8][1] = h2.y;
            C[n8][2] = h2.x; C[n8][3] = h2.y;
        }

#pragma unroll
        for (int ks = 0; ks < 4; ++ks) {
            const uint32_t kc = (uint32_t)((ks * 32 + ms * 16) ^ (r7 << 4));
#pragma unroll
            for (int t = 0; t < COMPS; ++t) {  // B component
                const uint32_t bbase = sb + SM_RING + (stage * COMPS + t) * BTILE
                                     + blane + kc;
                uint32_t Bt[4][4];             // 8 n8 frags (2 per LDSM_X4)
#pragma unroll
                for (int n16 = 0; n16 < 4; ++n16)
                    LDSM_X4(Bt[n16], bbase + (uint32_t)(n16 * 2048));
                // truncated product: t=0 -> h0,h1; t=1 -> h0 only
                // (h1*e1 ~ 2^-22, dropped)
#pragma unroll
                for (int at = 0; at < COMPS - t; ++at) {
#pragma unroll
                    for (int n16 = 0; n16 < 4; ++n16) {
                        MMA(C[2 * n16],     Af[at][ks], &Bt[n16][0]);
                        MMA(C[2 * n16 + 1], Af[at][ks], &Bt[n16][2]);
                    }
                }
            }
        }

        // epilogue: argmax over this chunk (codes ascending -> first-min tie)
#pragma unroll
        for (int n8 = 0; n8 < 8; ++n8) {
            const int code = c * N_CHUNK + n8 * 8 + colOff;
            if (C[n8][0] > best0) { best0 = C[n8][0]; bi0 = code; }
            if (C[n8][1] > best0) { best0 = C[n8][1]; bi0 = code + 1; }
            if (C[n8][2] > best1) { best1 = C[n8][2]; bi1 = code; }
            if (C[n8][3] > best1) { best1 = C[n8][3]; bi1 = code + 1; }
        }

        // end-of-chunk: ensure chunk c+1 arrived; one barrier publishes it
        // and retires this stage for reuse at c+4.
        if (c + 1 < CHUNKS) {
            if (c + 3 < CHUNKS) { CP_WAIT(2); } else { CP_WAIT(0); }
            __syncthreads();
        }
    }

    // cross-lane reduce among the 4 lanes sharing each row
#pragma unroll
    for (int off = 1; off <= 2; off <<= 1) {
        float v0 = __shfl_xor_sync(0xFFFFFFFFu, best0, off);
        int   i0 = __shfl_xor_sync(0xFFFFFFFFu, bi0,   off);
        if (v0 > best0 || (v0 == best0 && i0 < bi0)) { best0 = v0; bi0 = i0; }
        float v1 = __shfl_xor_sync(0xFFFFFFFFu, best1, off);
        int   i1 = __shfl_xor_sync(0xFFFFFFFFu, bi1,   off);
        if (v1 > best1 || (v1 == best1 && i1 < bi1)) { best1 = v1; bi1 = i1; }
    }
    if ((lane & 3) == 0) {
        const int r = lane >> 2;
        out[rowBase + wid * 16 + r]     = (float)bi0;
        out[rowBase + wid * 16 + r + 8] = (float)bi1;
    }
}

// ---------------------------------------------------------------------------
// Harness entry
// ---------------------------------------------------------------------------
extern "C" void kernel_launch(void* const* d_in, const int* in_sizes, int n_in,
                              void* d_out, int out_size) {
    const float* inp = (const float*)d_in[0];
    const float* cb  = (const float*)d_in[1];
    if (in_sizes[0] == NUM_CODES * DIM && in_sizes[1] != NUM_CODES * DIM) {
        const float* tmp = inp; inp = cb; cb = tmp;
    }
    float* out = (float*)d_out;

    cudaFuncSetAttribute(vq_mma_kernel,
                         cudaFuncAttributeMaxDynamicSharedMemorySize, SM_ALLOC);
    vq_prep<<<16, 256>>>(cb);
    vq_mma_kernel<<<N_ROWS / M_TILE, THREADS, SM_ALLOC>>>(inp, out);
}

// round 15
// speedup vs baseline: 2.0958x; 1.0786x over previous
#include <cuda_runtime.h>
#include <cuda_fp16.h>
#include <cstdint>

// VQ nearest-codebook search via warp-level mma.sync (HMMA, baseline PTX).
//   inputs [16,64,64,64] NCHW fp32, codebook [1024,64] fp32
//   out[n] (as float32) = argmin_k ||x_n - e_k||^2
//                       = argmax_k ( x_n.e_k - 0.5||e_k||^2 )
// fp16 pair-split, 3 MMA passes (h0e0 + h1e0 + h0e1), exact fp32 norms.
// R15: per-stage mbarrier producer/consumer ring replaces the per-chunk
// __syncthreads lockstep — warps drift up to 3 chunks, epilogue/LDSM of one
// warp overlaps MMA of others (de-convoys the tensor pipe).

#define NUM_CODES 1024
#define DIM       64
#define M_TILE    128
#define N_CHUNK   64
#define CHUNKS    16
#define THREADS   256
#define N_ROWS    65536
#define HW        4096
#define ATILE     16384            // [128 rows][64 fp16] A tile (prologue only)
#define BTILE     8192             // [64 codes][64 fp16] B tile
#define STAGES    4
#define COMPS     2

// smem layout (relative to 1024-aligned base)
#define SM_H      0                          // 1024 floats (-0.5||e||^2)
#define SM_RING   4096                       // 4 stages x 2 comps x 8 KB = 64 KB
#define SM_A      SM_RING                    // A built here, freed after Af load
#define SM_MB     (SM_RING + STAGES * COMPS * BTILE)   // 69632: mbarriers
#define SM_TOTAL  (SM_MB + 64)
#define SM_ALLOC  (SM_TOTAL + 1024)

#define MB_FULL(s)  (sb + SM_MB + (s) * 8)
#define MB_EMPTY(s) (sb + SM_MB + 32 + (s) * 8)

__device__ float g_h[NUM_CODES];                       // -0.5*||e_k||^2
__device__ __align__(16) unsigned char g_bsplit[COMPS * CHUNKS * BTILE];

#define SW128(o) ((o) ^ (((o) >> 3) & 0x70))

__device__ __forceinline__ uint32_t smem_u32(const void* p) {
    uint32_t a;
    asm("{ .reg .u64 t; cvta.to.shared.u64 t, %1; cvt.u32.u64 %0, t; }"
        : "=r"(a) : "l"(p));
    return a;
}

#define LDSM_X4(r, a) \
    asm volatile("ldmatrix.sync.aligned.m8n8.x4.shared.b16 {%0,%1,%2,%3}, [%4];" \
        : "=r"((r)[0]), "=r"((r)[1]), "=r"((r)[2]), "=r"((r)[3]) : "r"(a))
#define MMA(c, A, B) \
    asm volatile("mma.sync.aligned.m16n8k16.row.col.f32.f16.f16.f32 " \
        "{%0,%1,%2,%3}, {%4,%5,%6,%7}, {%8,%9}, {%0,%1,%2,%3};" \
        : "+f"((c)[0]), "+f"((c)[1]), "+f"((c)[2]), "+f"((c)[3]) \
        : "r"((A)[0]), "r"((A)[1]), "r"((A)[2]), "r"((A)[3]), \
          "r"((B)[0]), "r"((B)[1]))
#define CP16(dst, src) \
    asm volatile("cp.async.cg.shared.global [%0], [%1], 16;" :: "r"(dst), "l"(src))

// mbarrier (baseline sm_90 PTX, no 'a' features)
#define MB_INIT(m, cnt) \
    asm volatile("mbarrier.init.shared.b64 [%0], %1;" :: "r"(m), "r"(cnt) : "memory")
#define MB_ARRIVE(m) \
    asm volatile("{ .reg .b64 t; mbarrier.arrive.shared.b64 t, [%0]; }" :: "r"(m) : "memory")
#define CP_MB_ARRIVE(m) \
    asm volatile("cp.async.mbarrier.arrive.noinc.shared.b64 [%0];" :: "r"(m) : "memory")
#define MB_WAIT(m, ph) do {                                                     \
    uint32_t _m = (m), _p = (ph), _d;                                           \
    asm volatile("{ .reg .pred p; mbarrier.try_wait.parity.shared.b64 p, [%1], %2; selp.b32 %0,1,0,p; }" \
                 : "=r"(_d) : "r"(_m), "r"(_p) : "memory");                     \
    while (!_d) {                                                               \
        asm volatile("{ .reg .pred p; mbarrier.try_wait.parity.shared.b64 p, [%1], %2, 0x989680; selp.b32 %0,1,0,p; }" \
                     : "=r"(_d) : "r"(_m), "r"(_p) : "memory");                 \
    }                                                                           \
} while (0)

__device__ __forceinline__ uint32_t pack_h2(__half lo, __half hi) {
    return ((uint32_t)__half_as_ushort(hi) << 16) | __half_as_ushort(lo);
}
__device__ __forceinline__ void split2(float x, __half& c0, __half& c1) {
    c0 = __float2half_rn(x);
    c1 = __float2half_rn(x - __half2float(c0));
}

// ---------------------------------------------------------------------------
// Prep: split codebook into 2 fp16 comps, pre-swizzled [64-code] tiles; norms.
// ---------------------------------------------------------------------------
__global__ void vq_prep(const float* __restrict__ cb) {
    int g = blockIdx.x * blockDim.x + threadIdx.x;   // 0..4095
    int j = g >> 2;                                  // code
    int q = g & 3;                                   // dim quarter
    int chunk = j >> 6, jr = j & 63;
    float nrm = 0.f;
#pragma unroll
    for (int i = 0; i < 8; ++i) {
        int dp = q * 8 + i;                          // dim pair
        float x0 = cb[(size_t)j * DIM + 2 * dp];
        float x1 = cb[(size_t)j * DIM + 2 * dp + 1];
        nrm = fmaf(x0, x0, nrm);
        nrm = fmaf(x1, x1, nrm);
        __half a0, a1, b0, b1;
        split2(x0, a0, a1);
        split2(x1, b0, b1);
        uint32_t sw = SW128((uint32_t)(jr * 128 + dp * 4));
        *(uint32_t*)&g_bsplit[(0 * CHUNKS + chunk) * BTILE + sw] = pack_h2(a0, b0);
        *(uint32_t*)&g_bsplit[(1 * CHUNKS + chunk) * BTILE + sw] = pack_h2(a1, b1);
    }
    nrm += __shfl_xor_sync(0xFFFFFFFFu, nrm, 1);
    nrm += __shfl_xor_sync(0xFFFFFFFFu, nrm, 2);
    if (q == 0) g_h[j] = -0.5f * nrm;
}

// ---------------------------------------------------------------------------
// Main kernel
// ---------------------------------------------------------------------------
// produce chunk c into stage: this thread's 4 CP16 + cp-completion arrive.
__device__ __forceinline__ void produce(uint32_t sb, int c, int stage, int tid) {
#pragma unroll
    for (int t = 0; t < COMPS; ++t) {
#pragma unroll
        for (int i = 0; i < 2; ++i) {       // 512 float4 per 8KB tile
            int idx = i * THREADS + tid;
            uint32_t dst = sb + SM_RING + (stage * COMPS + t) * BTILE + idx * 16;
            const unsigned char* src = &g_bsplit[(t * CHUNKS + c) * BTILE + idx * 16];
            CP16(dst, src);
        }
    }
    CP_MB_ARRIVE(MB_FULL(stage));
}

__global__ __launch_bounds__(THREADS, 2)
void vq_mma_kernel(const float* __restrict__ in, float* __restrict__ out) {
    extern __shared__ char smraw[];
    const uint32_t sbr = smem_u32(smraw);
    const uint32_t sb  = (sbr + 1023u) & ~1023u;    // 1K-align for swizzle
    char* sm = smraw + (sb - sbr);

    const int tid  = threadIdx.x;
    const int wid  = tid >> 5;
    const int lane = tid & 31;

    // mbarrier init: full = 256 cp-completion arrivals, empty = 8 warp arrivals
    if (tid == 0) {
#pragma unroll
        for (int s = 0; s < STAGES; ++s) {
            MB_INIT(MB_FULL(s), THREADS);
            MB_INIT(MB_EMPTY(s), 8);
        }
    }

    // -0.5||e||^2 -> smem
    float* sh = (float*)(sm + SM_H);
    for (int i = tid; i < NUM_CODES; i += THREADS) sh[i] = g_h[i];

    // build A (in ring space; freed after Af load): 128 rows x 64 ch
    const int rowBase = blockIdx.x * M_TILE;
    const int b   = rowBase >> 12;
    const int hw0 = rowBase & (HW - 1);
    const float* xin = in + ((size_t)b * DIM * HW) + hw0;
#pragma unroll
    for (int i = 0; i < 16; ++i) {
        int idx = i * THREADS + tid;
        int r = idx & 127, dp = idx >> 7;
        float x0 = xin[(size_t)(2 * dp) * HW + r];
        float x1 = xin[(size_t)(2 * dp + 1) * HW + r];
        __half a0, a1, b0, b1;
        split2(x0, a0, a1);
        split2(x1, b0, b1);
        uint32_t sw = SW128((uint32_t)(r * 128 + dp * 4));
        *(uint32_t*)(sm + SM_A + 0 * ATILE + sw) = pack_h2(a0, b0);
        *(uint32_t*)(sm + SM_A + 1 * ATILE + sw) = pack_h2(a1, b1);
    }
    __syncthreads();      // A ready (also publishes mbarrier init)

    // A fragments in registers: warp w = rows w*16..w*16+15.  32 regs.
    uint32_t Af[COMPS][4][4];
    {
        const int arow = wid * 16 + (lane & 15);
        const uint32_t colb = (uint32_t)((lane >> 4) * 16);
#pragma unroll
        for (int t = 0; t < COMPS; ++t)
#pragma unroll
            for (int ks = 0; ks < 4; ++ks) {
                uint32_t off = (uint32_t)(arow * 128)
                             + ((colb + ks * 32) ^ ((uint32_t)(arow & 7) << 4));
                LDSM_X4(Af[t][ks], sb + SM_A + t * ATILE + off);
            }
    }
    __syncthreads();      // all Af loads done; ring space free for cp

    // producer cursor: starts phase 1 (first STAGES empty-waits pass).
    int pstage = 0, pphase = 1;
    // consumer cursor: starts phase 0.
    int cstage = 0, cphase = 0;

    // prologue: produce chunks 0..2 into stages 0..2
#pragma unroll
    for (int c = 0; c < 3; ++c) {
        MB_WAIT(MB_EMPTY(pstage), pphase);
        produce(sb, c, pstage, tid);
        if (++pstage == STAGES) { pstage = 0; pphase ^= 1; }
    }

    // B ldmatrix.x4 lane geometry
    const int r7 = lane & 7;
    const int ms = (lane >> 3) & 1;
    const int j2 = lane >> 4;
    const uint32_t blane = (uint32_t)(j2 * 1024 + r7 * 128);
    const int colOff = 2 * (lane & 3);

    float best0 = -3.402823466e38f, best1 = -3.402823466e38f;
    int   bi0 = 0, bi1 = 0;

    for (int c = 0; c < CHUNKS; ++c) {
        const int stage = cstage;
        MB_WAIT(MB_FULL(stage), cphase);
        if (++cstage == STAGES) { cstage = 0; cphase ^= 1; }

        // C init = -0.5||e||^2
        float C[8][4];
#pragma unroll
        for (int n8 = 0; n8 < 8; ++n8) {
            float2 h2 = *(const float2*)&sh[c * N_CHUNK + n8 * 8 + colOff];
            C[n8][0] = h2.x; C[n8][1] = h2.y;
            C[n8][2] = h2.x; C[n8][3] = h2.y;
        }

#pragma unroll
        for (int ks = 0; ks < 4; ++ks) {
            const uint32_t kc = (uint32_t)((ks * 32 + ms * 16) ^ (r7 << 4));
#pragma unroll
            for (int t = 0; t < COMPS; ++t) {  // B component
                const uint32_t bbase = sb + SM_RING + (stage * COMPS + t) * BTILE
                                     + blane + kc;
                uint32_t Bt[4][4];             // 8 n8 frags (2 per LDSM_X4)
#pragma unroll
                for (int n16 = 0; n16 < 4; ++n16)
                    LDSM_X4(Bt[n16], bbase + (uint32_t)(n16 * 2048));
                // truncated product: t=0 -> h0,h1; t=1 -> h0 only
#pragma unroll
                for (int at = 0; at < COMPS - t; ++at) {
#pragma unroll
                    for (int n16 = 0; n16 < 4; ++n16) {
                        MMA(C[2 * n16],     Af[at][ks], &Bt[n16][0]);
                        MMA(C[2 * n16 + 1], Af[at][ks], &Bt[n16][2]);
                    }
                }
            }
        }

        // this warp is done reading the stage -> release it
        __syncwarp();
        if (lane == 0) MB_ARRIVE(MB_EMPTY(stage));

        // produce chunk c+3 (stage retired after chunk c-1's consumption)
        if (c + 3 < CHUNKS) {
            MB_WAIT(MB_EMPTY(pstage), pphase);
            produce(sb, c + 3, pstage, tid);
            if (++pstage == STAGES) { pstage = 0; pphase ^= 1; }
        }

        // epilogue: argmax over this chunk (codes ascending -> first-min tie)
#pragma unroll
        for (int n8 = 0; n8 < 8; ++n8) {
            const int code = c * N_CHUNK + n8 * 8 + colOff;
            if (C[n8][0] > best0) { best0 = C[n8][0]; bi0 = code; }
            if (C[n8][1] > best0) { best0 = C[n8][1]; bi0 = code + 1; }
            if (C[n8][2] > best1) { best1 = C[n8][2]; bi1 = code; }
            if (C[n8][3] > best1) { best1 = C[n8][3]; bi1 = code + 1; }
        }
    }

    // cross-lane reduce among the 4 lanes sharing each row
#pragma unroll
    for (int off = 1; off <= 2; off <<= 1) {
        float v0 = __shfl_xor_sync(0xFFFFFFFFu, best0, off);
        int   i0 = __shfl_xor_sync(0xFFFFFFFFu, bi0,   off);
        if (v0 > best0 || (v0 == best0 && i0 < bi0)) { best0 = v0; bi0 = i0; }
        float v1 = __shfl_xor_sync(0xFFFFFFFFu, best1, off);
        int   i1 = __shfl_xor_sync(0xFFFFFFFFu, bi1,   off);
        if (v1 > best1 || (v1 == best1 && i1 < bi1)) { best1 = v1; bi1 = i1; }
    }
    if ((lane & 3) == 0) {
        const int r = lane >> 2;
        out[rowBase + wid * 16 + r]     = (float)bi0;
        out[rowBase + wid * 16 + r + 8] = (float)bi1;
    }
}

// ---------------------------------------------------------------------------
// Harness entry
// ---------------------------------------------------------------------------
extern "C" void kernel_launch(void* const* d_in, const int* in_sizes, int n_in,
                              void* d_out, int out_size) {
    const float* inp = (const float*)d_in[0];
    const float* cb  = (const float*)d_in[1];
    if (in_sizes[0] == NUM_CODES * DIM && in_sizes[1] != NUM_CODES * DIM) {
        const float* tmp = inp; inp = cb; cb = tmp;
    }
    float* out = (float*)d_out;

    cudaFuncSetAttribute(vq_mma_kernel,
                         cudaFuncAttributeMaxDynamicSharedMemorySize, SM_ALLOC);
    vq_prep<<<16, 256>>>(cb);
    vq_mma_kernel<<<N_ROWS / M_TILE, THREADS, SM_ALLOC>>>(inp, out);
}